// round 10
// baseline (speedup 1.0000x reference)
#include <cuda_runtime.h>
#include <cuda_fp16.h>

#define LN 1024
#define NB 16
#define NC 512
#define KN 8
#define NCP (NC/2)
#define SHSZ 1056

// per-stage conflict-free exchange swizzle (see analysis):
//  t=0: additive pad (stride-4 stores)   t=1: XOR bits2-3 (4-way fix)
//  t=2: XOR bit4 (2-way fix)             t=3: identity (stride-1 stores)
__device__ __forceinline__ int swz(int t, int i){
    if (t == 0) return i + (i >> 5);
    if (t == 1) return i ^ (((i >> 5) & 3) << 2);
    if (t == 2) return i ^ (((i >> 6) & 1) << 4);
    return i;
}

// ---------------- device scratch (statically allocated; no runtime allocs) ----------------
__device__ float2  d_tw[LN];                 // forward twiddles e^{-2pi i j/1024}
__device__ float   d_s[NB * LN];             // channel-sum of x
__device__ float2  d_qf[NB * LN];            // fft(q)
__device__ float   d_w[NB * KN * LN];        // blend weights, PRE-SCALED by 1/1024
__device__ float   d_p[NB * KN * LN];        // P = ifft((1-w)*qfft).real
__device__ float   d_sum[LN];                // BN sum per l
__device__ float   d_sq[LN];                 // BN sumsq per l
__device__ float   d_scale[LN];
__device__ float   d_shift[LN];
__device__ __half2 d_o[(size_t)NB * NCP * KN * LN];   // 128 MB o scratch, (c0,c1) packed

// ---------------- complex helpers ----------------
__device__ __forceinline__ float2 cadd(float2 a, float2 b){ return make_float2(a.x+b.x, a.y+b.y); }
__device__ __forceinline__ float2 csub(float2 a, float2 b){ return make_float2(a.x-b.x, a.y-b.y); }
__device__ __forceinline__ float2 cmul(float2 a, float2 b){ return make_float2(a.x*b.x - a.y*b.y, a.x*b.y + a.y*b.x); }

template<bool INV>
__device__ __forceinline__ float2 twg(int e){
    float2 t = d_tw[e & 1023];
    if (INV) t.y = -t.y;
    return t;
}

// =================== block-cooperative radix-4 Stockham FFT, single stream ===================
// 256 threads, 4 pts/thread, ping-pong buffers, 1 barrier per exchange.
template<bool INV>
__device__ __forceinline__ void fft1024(float2 a[4],
                                        float* s0re, float* s0im,
                                        float* s1re, float* s1im, int u){
    #pragma unroll
    for (int t = 0; t < 5; t++){
        int s = 1 << (2*t);
        int q = u & (s - 1);
        int e = u - q;
        float2 b0 = cadd(a[0], a[2]);
        float2 b1 = csub(a[0], a[2]);
        float2 b2 = cadd(a[1], a[3]);
        float2 b3 = csub(a[1], a[3]);
        float2 jb3 = INV ? make_float2(-b3.y, b3.x) : make_float2(b3.y, -b3.x);
        float2 c0 = cadd(b0, b2);
        float2 c1 = cmul(cadd(b1, jb3), twg<INV>(e));
        float2 c2 = cmul(csub(b0, b2), twg<INV>(2*e));
        float2 c3 = cmul(csub(b1, jb3), twg<INV>(3*e));
        if (t < 4){
            float* wre = (t & 1) ? s1re : s0re;
            float* wim = (t & 1) ? s1im : s0im;
            int base = 4*u - 3*q;
            wre[swz(t, base      )] = c0.x;  wim[swz(t, base      )] = c0.y;
            wre[swz(t, base +   s)] = c1.x;  wim[swz(t, base +   s)] = c1.y;
            wre[swz(t, base + 2*s)] = c2.x;  wim[swz(t, base + 2*s)] = c2.y;
            wre[swz(t, base + 3*s)] = c3.x;  wim[swz(t, base + 3*s)] = c3.y;
            __syncthreads();
            #pragma unroll
            for (int c = 0; c < 4; c++){
                int idx = swz(t, u + 256*c);
                a[c] = make_float2(wre[idx], wim[idx]);
            }
        } else {
            a[0] = c0; a[1] = c1; a[2] = c2; a[3] = c3;
        }
    }
}

// =================== dual-stream version: two independent FFTs, shared barriers ===================
template<bool INV>
__device__ __forceinline__ void fft1024x2(float2 a[4], float2 b[4],
        float* a0r, float* a0i, float* a1r, float* a1i,
        float* b0r, float* b0i, float* b1r, float* b1i, int u){
    #pragma unroll
    for (int t = 0; t < 5; t++){
        int s = 1 << (2*t);
        int q = u & (s - 1);
        int e = u - q;
        float2 w1 = twg<INV>(e);
        float2 w2 = twg<INV>(2*e);
        float2 w3 = twg<INV>(3*e);
        // stream A
        float2 A0 = cadd(a[0], a[2]);
        float2 A1 = csub(a[0], a[2]);
        float2 A2 = cadd(a[1], a[3]);
        float2 A3 = csub(a[1], a[3]);
        float2 jA3 = INV ? make_float2(-A3.y, A3.x) : make_float2(A3.y, -A3.x);
        float2 ca0 = cadd(A0, A2);
        float2 ca1 = cmul(cadd(A1, jA3), w1);
        float2 ca2 = cmul(csub(A0, A2), w2);
        float2 ca3 = cmul(csub(A1, jA3), w3);
        // stream B
        float2 B0 = cadd(b[0], b[2]);
        float2 B1 = csub(b[0], b[2]);
        float2 B2 = cadd(b[1], b[3]);
        float2 B3 = csub(b[1], b[3]);
        float2 jB3 = INV ? make_float2(-B3.y, B3.x) : make_float2(B3.y, -B3.x);
        float2 cb0 = cadd(B0, B2);
        float2 cb1 = cmul(cadd(B1, jB3), w1);
        float2 cb2 = cmul(csub(B0, B2), w2);
        float2 cb3 = cmul(csub(B1, jB3), w3);
        if (t < 4){
            float* wra = (t & 1) ? a1r : a0r;
            float* wia = (t & 1) ? a1i : a0i;
            float* wrb = (t & 1) ? b1r : b0r;
            float* wib = (t & 1) ? b1i : b0i;
            int base = 4*u - 3*q;
            int i0 = swz(t, base      );
            int i1 = swz(t, base +   s);
            int i2 = swz(t, base + 2*s);
            int i3 = swz(t, base + 3*s);
            wra[i0] = ca0.x;  wia[i0] = ca0.y;
            wra[i1] = ca1.x;  wia[i1] = ca1.y;
            wra[i2] = ca2.x;  wia[i2] = ca2.y;
            wra[i3] = ca3.x;  wia[i3] = ca3.y;
            wrb[i0] = cb0.x;  wib[i0] = cb0.y;
            wrb[i1] = cb1.x;  wib[i1] = cb1.y;
            wrb[i2] = cb2.x;  wib[i2] = cb2.y;
            wrb[i3] = cb3.x;  wib[i3] = cb3.y;
            __syncthreads();
            #pragma unroll
            for (int c = 0; c < 4; c++){
                int idx = swz(t, u + 256*c);
                a[c] = make_float2(wra[idx], wia[idx]);
                b[c] = make_float2(wrb[idx], wib[idx]);
            }
        } else {
            a[0] = ca0; a[1] = ca1; a[2] = ca2; a[3] = ca3;
            b[0] = cb0; b[1] = cb1; b[2] = cb2; b[3] = cb3;
        }
    }
}

// ---------------- kernels ----------------

__global__ void k_init(){
    int i = blockIdx.x * 256 + threadIdx.x;
    if (i < LN){
        double ang = -2.0 * 3.14159265358979323846 * (double)i / 1024.0;
        d_tw[i] = make_float2((float)cos(ang), (float)sin(ang));
        d_sum[i] = 0.f;
        d_sq[i]  = 0.f;
    }
    if (i < NB * LN) d_s[i] = 0.0f;
}

// fused: blocks [0,64) do the channel-sum of x; blocks [64,80) do fft(q)
__global__ void k_sumqf(const float* __restrict__ x, const float* __restrict__ q){
    __shared__ float s0re[SHSZ], s0im[SHSZ], s1re[SHSZ], s1im[SHSZ];
    int u = threadIdx.x;
    if (blockIdx.x < 64){
        int b  = blockIdx.x >> 2;
        int cg = blockIdx.x & 3;
        float acc[4] = {0.f, 0.f, 0.f, 0.f};
        const float* xb = x + ((size_t)b * NC + (size_t)cg * 128) * LN;
        for (int c = 0; c < 128; c++){
            #pragma unroll
            for (int j = 0; j < 4; j++) acc[j] += xb[(size_t)c * LN + u + 256*j];
        }
        #pragma unroll
        for (int j = 0; j < 4; j++) atomicAdd(&d_s[b * LN + u + 256*j], acc[j]);
    } else {
        int b = blockIdx.x - 64;
        float2 a[4];
        #pragma unroll
        for (int j = 0; j < 4; j++) a[j] = make_float2(q[b * LN + u + 256*j], 0.f);
        fft1024<false>(a, s0re, s0im, s1re, s1im, u);
        #pragma unroll
        for (int j = 0; j < 4; j++) d_qf[b * LN + u + 256*j] = a[j];
    }
}

__global__ void k_stats(const float* __restrict__ q,
                        const float* __restrict__ sig,
                        const float* __restrict__ csh){
    __shared__ float s0re[SHSZ], s0im[SHSZ], s1re[SHSZ], s1im[SHSZ];
    __shared__ float gsh[16];
    __shared__ float ssb[LN];
    __shared__ float red[32];
    __shared__ float scal[4];
    int k = blockIdx.x, b = blockIdx.y, u = threadIdx.x;

    float sg = sig[k] + 0.001f;
    float cc = csh[k];
    if (u < 15){
        float t = (float)u - 7.0f - cc;
        gsh[u] = expf(-0.5f * (t / sg) * (t / sg));
    }
    #pragma unroll
    for (int j = 0; j < 4; j++) ssb[u + 256*j] = d_s[b * LN + u + 256*j];
    __syncthreads();

    float gs = 0.f;
    #pragma unroll
    for (int j = 0; j < 15; j++) gs += gsh[j];
    float g[15];
    float ginv = 1.0f / (gs + 0.01f);
    #pragma unroll
    for (int j = 0; j < 15; j++) g[j] = gsh[j] * ginv;

    float2 a[4];
    #pragma unroll
    for (int c = 0; c < 4; c++){
        int l = u + 256*c;
        float bl = 0.f;
        #pragma unroll
        for (int j = 0; j < 15; j++){
            int idx = l + j - 7;
            idx = idx < 0 ? 0 : (idx > LN-1 ? LN-1 : idx);
            bl += ssb[idx] * g[j];
        }
        a[c] = make_float2(bl, 0.f);
    }

    if (u == 0){
        float mxs = 0.f, mys = 0.f;
        for (int bb2 = 0; bb2 < NB; bb2++){
            float bl0 = 0.f;
            #pragma unroll
            for (int j = 0; j < 15; j++){
                int idx = j - 7; if (idx < 0) idx = 0;
                bl0 += d_s[bb2 * LN + idx] * g[j];
            }
            mxs += bl0;
            mys += q[bb2 * LN];
        }
        scal[0] = mxs * (1.0f/16.0f);
        scal[1] = mys * (1.0f/16.0f);
    }
    __syncthreads();

    fft1024<false>(a, s0re, s0im, s1re, s1im, u);

    float2 qf[4];
    #pragma unroll
    for (int c = 0; c < 4; c++) qf[c] = d_qf[b * LN + u + 256*c];

    float mx = scal[0], my = scal[1];

    float v0 = 0.f, v1 = 0.f, v2 = 0.f, v3 = 0.f;
    #pragma unroll
    for (int c = 0; c < 4; c++){
        float2 vm = a[c];  vm.x -= mx;
        float2 t  = cmul(vm, vm);
        v0 += t.x; v1 += t.y;
        float2 qm = qf[c]; qm.x -= mx;
        t = cmul(qm, qm);
        v2 += t.x; v3 += t.y;
    }
    #pragma unroll
    for (int o = 16; o > 0; o >>= 1){
        v0 += __shfl_down_sync(0xffffffffu, v0, o);
        v1 += __shfl_down_sync(0xffffffffu, v1, o);
        v2 += __shfl_down_sync(0xffffffffu, v2, o);
        v3 += __shfl_down_sync(0xffffffffu, v3, o);
    }
    if ((u & 31) == 0){
        int w = u >> 5;
        red[w*4+0] = v0; red[w*4+1] = v1; red[w*4+2] = v2; red[w*4+3] = v3;
    }
    __syncthreads();
    float2 AS = make_float2(0.f, 0.f), BS = make_float2(0.f, 0.f);
    #pragma unroll
    for (int w = 0; w < 8; w++){
        AS.x += red[w*4+0]; AS.y += red[w*4+1];
        BS.x += red[w*4+2]; BS.y += red[w*4+3];
    }
    float2 dd = cmul(AS, BS);
    dd.x += 0.001f;
    float dinv = rsqrtf(dd.x*dd.x + dd.y*dd.y);

    float2 pa[4];
    #pragma unroll
    for (int c = 0; c < 4; c++){
        float2 vm = a[c];  vm.x -= mx;
        float2 qm = qf[c]; qm.x -= my;
        float2 cov = cmul(vm, qm);
        float cm = sqrtf(cov.x*cov.x + cov.y*cov.y);
        float wv = 1.0f - expf(-0.1f * cm * dinv);
        // pre-scale by 1/1024 so k_main's ifft output needs no normalization
        d_w[(b * KN + k) * LN + u + 256*c] = wv * (1.0f/1024.0f);
        float om = 1.0f - wv;
        pa[c] = make_float2(om * qf[c].x, om * qf[c].y);
    }
    __syncthreads();
    fft1024<true>(pa, s0re, s0im, s1re, s1im, u);
    #pragma unroll
    for (int c = 0; c < 4; c++)
        d_p[(b * KN + k) * LN + u + 256*c] = pa[c].x * (1.0f/1024.0f);
}

// -------- main kernel: block per channel pair; two inverse FFTs interleaved --------
// Natural register allocation (R8 lesson: forcing low regs spills into the hot L1 pipe).
__global__ void __launch_bounds__(256) k_main(const float* __restrict__ x){
    __shared__ float A0r[SHSZ], A0i[SHSZ], A1r[SHSZ], A1i[SHSZ];
    __shared__ float B0r[SHSZ], B0i[SHSZ], B1r[SHSZ], B1i[SHSZ];
    int cp = blockIdx.x;
    int b  = blockIdx.y;
    int u  = threadIdx.x;
    const float* x0 = x + ((size_t)b * NC + 2*cp    ) * LN;
    const float* x1 = x + ((size_t)b * NC + 2*cp + 1) * LN;

    float xa[4], xb[4];
    float2 z[4];
    #pragma unroll
    for (int j = 0; j < 4; j++){
        xa[j] = x0[u + 256*j];
        xb[j] = x1[u + 256*j];
        z[j] = make_float2(xa[j], xb[j]);
    }
    fft1024<false>(z, A0r, A0i, A1r, A1i, u);   // Z = X0 + i*X1

    float sm[4] = {0,0,0,0}, sq[4] = {0,0,0,0};
    __half2* ob = d_o + ((size_t)(b * NCP + cp)) * KN * LN;
    const float* wb = d_w + (size_t)b * KN * LN;
    const float* pb = d_p + (size_t)b * KN * LN;

    for (int k = 0; k < KN; k += 2){
        float2 a[4], bb[4];
        #pragma unroll
        for (int j = 0; j < 4; j++){
            int l = u + 256*j;
            float wv0 = wb[ k      * LN + l];
            float wv1 = wb[(k + 1) * LN + l];
            a[j]  = make_float2(z[j].x * wv0, z[j].y * wv0);
            bb[j] = make_float2(z[j].x * wv1, z[j].y * wv1);
        }
        fft1024x2<true>(a, bb, A0r, A0i, A1r, A1i, B0r, B0i, B1r, B1i, u);
        #pragma unroll
        for (int j = 0; j < 4; j++){
            int l = u + 256*j;
            float pp0 = pb[ k      * LN + l];
            float pp1 = pb[(k + 1) * LN + l];
            float o0 = fabsf(a[j].x  + pp0) + xa[j];   // w pre-scaled by 1/1024
            float o1 = fabsf(a[j].y  + pp0) + xb[j];
            float o2 = fabsf(bb[j].x + pp1) + xa[j];
            float o3 = fabsf(bb[j].y + pp1) + xb[j];
            ob[ k      * LN + l] = __floats2half2_rn(o0, o1);
            ob[(k + 1) * LN + l] = __floats2half2_rn(o2, o3);
            sm[j] += (o0 + o1) + (o2 + o3);
            sq[j] += (o0*o0 + o1*o1) + (o2*o2 + o3*o3);
        }
        // no trailing barrier needed: stage-3 barrier of this call separates the
        // last reads of buffer set 0 from the next iteration's stage-0 writes.
    }
    #pragma unroll
    for (int j = 0; j < 4; j++){
        atomicAdd(&d_sum[u + 256*j], sm[j]);
        atomicAdd(&d_sq[u + 256*j],  sq[j]);
    }
}

__global__ void k_bn(const float* __restrict__ gamma, const float* __restrict__ beta){
    int l = blockIdx.x * 256 + threadIdx.x;
    if (l < LN){
        float cnt  = (float)(NB * NC * KN);   // 65536
        float mean = d_sum[l] / cnt;
        float var  = d_sq[l] / cnt - mean * mean;
        float sc = gamma[l] * rsqrtf(var + 1e-5f);
        d_scale[l] = sc;
        d_shift[l] = beta[l] - mean * sc;
    }
}

__global__ void __launch_bounds__(256) k_attn(const float* __restrict__ q, float* __restrict__ out){
    __shared__ float red[8 * 16];
    int cp = blockIdx.x, b = blockIdx.y, u = threadIdx.x;
    const __half2* ob = d_o + ((size_t)(b * NCP + cp)) * KN * LN;

    float qa[4], sc[4], sh[4];
    #pragma unroll
    for (int j = 0; j < 4; j++){
        int l = u + 256*j;
        float sl = d_scale[l];
        qa[j] = q[b * LN + l] * sl;
        sc[j] = sl;
        sh[j] = d_shift[l];
    }
    __half2 ov[KN][4];
    float s0[KN], s1[KN];
    #pragma unroll
    for (int k = 0; k < KN; k++){ s0[k] = 0.f; s1[k] = 0.f; }
    #pragma unroll
    for (int k = 0; k < KN; k++){
        #pragma unroll
        for (int j = 0; j < 4; j++){
            __half2 h = ob[k * LN + u + 256*j];
            ov[k][j] = h;
            float2 f = __half22float2(h);
            s0[k] += qa[j] * f.x;
            s1[k] += qa[j] * f.y;
        }
    }
    #pragma unroll
    for (int k = 0; k < KN; k++){
        #pragma unroll
        for (int o = 16; o > 0; o >>= 1){
            s0[k] += __shfl_down_sync(0xffffffffu, s0[k], o);
            s1[k] += __shfl_down_sync(0xffffffffu, s1[k], o);
        }
    }
    if ((u & 31) == 0){
        int w = u >> 5;
        #pragma unroll
        for (int k = 0; k < KN; k++){
            red[w * 16 + k]     = s0[k];
            red[w * 16 + 8 + k] = s1[k];
        }
    }
    __syncthreads();
    float t0[KN], t1[KN];
    #pragma unroll
    for (int k = 0; k < KN; k++){
        float a0 = 0.f, a1 = 0.f;
        #pragma unroll
        for (int w = 0; w < 8; w++){
            a0 += red[w * 16 + k];
            a1 += red[w * 16 + 8 + k];
        }
        t0[k] = a0; t1[k] = a1;
    }
    float m0 = t0[0], m1 = t1[0];
    #pragma unroll
    for (int k = 1; k < KN; k++){ m0 = fmaxf(m0, t0[k]); m1 = fmaxf(m1, t1[k]); }
    float a0[KN], a1[KN], se0 = 0.f, se1 = 0.f;
    #pragma unroll
    for (int k = 0; k < KN; k++){
        a0[k] = expf(t0[k] - m0); se0 += a0[k];
        a1[k] = expf(t1[k] - m1); se1 += a1[k];
    }
    float i0 = 1.0f / se0, i1 = 1.0f / se1;
    float* o0p = out + ((size_t)b * NC + 2*cp    ) * LN;
    float* o1p = out + ((size_t)b * NC + 2*cp + 1) * LN;
    #pragma unroll
    for (int j = 0; j < 4; j++){
        float acc0 = 0.f, acc1 = 0.f;
        #pragma unroll
        for (int k = 0; k < KN; k++){
            float2 f = __half22float2(ov[k][j]);
            acc0 += a0[k] * f.x;
            acc1 += a1[k] * f.y;
        }
        int l = u + 256*j;
        o0p[l] = sc[j] * (acc0 * i0) + sh[j];
        o1p[l] = sc[j] * (acc1 * i1) + sh[j];
    }
}

extern "C" void kernel_launch(void* const* d_in, const int* in_sizes, int n_in,
                              void* d_out, int out_size){
    const float* x     = (const float*)d_in[0];
    const float* q     = (const float*)d_in[1];
    const float* sig   = (const float*)d_in[2];
    const float* csh   = (const float*)d_in[3];
    const float* gamma = (const float*)d_in[4];
    const float* beta  = (const float*)d_in[5];
    float* out = (float*)d_out;

    k_init <<<64, 256>>>();
    k_sumqf<<<80, 256>>>(x, q);
    k_stats<<<dim3(KN, NB), 256>>>(q, sig, csh);
    k_main <<<dim3(NCP, NB), 256>>>(x);
    k_bn   <<<4, 256>>>(gamma, beta);
    k_attn <<<dim3(NCP, NB), 256>>>(q, out);
}

// round 11
// speedup vs baseline: 1.3216x; 1.3216x over previous
#include <cuda_runtime.h>
#include <cuda_fp16.h>

#define LN 1024
#define NB 16
#define NC 512
#define KN 8
#define NCP (NC/2)
#define SHSZ 1056

// per-stage conflict-free exchange swizzle:
//  t=0: additive pad (stride-4 stores)   t=1: XOR bits2-3 (4-way fix)
//  t=2: XOR bit4 (2-way fix)             t=3: identity (stride-1 stores)
// t is a compile-time constant after loop unrolling -> branches fold.
__device__ __forceinline__ int swz(int t, int i){
    if (t == 0) return i + (i >> 5);
    if (t == 1) return i ^ (((i >> 5) & 3) << 2);
    if (t == 2) return i ^ (((i >> 6) & 1) << 4);
    return i;
}

// ---------------- device scratch (statically allocated; no runtime allocs) ----------------
__device__ float2  d_tw[LN];                 // forward twiddles e^{-2pi i j/1024}
__device__ float   d_s[NB * LN];             // channel-sum of x
__device__ float2  d_qf[NB * LN];            // fft(q)
__device__ float   d_w[NB * KN * LN];        // blend weights, PRE-SCALED by 1/1024
__device__ float   d_p[NB * KN * LN];        // P = ifft((1-w)*qfft).real
__device__ float   d_sum[LN];                // BN sum per l
__device__ float   d_sq[LN];                 // BN sumsq per l
__device__ float   d_scale[LN];
__device__ float   d_shift[LN];
__device__ __half2 d_o[(size_t)NB * NCP * KN * LN];   // 128 MB o scratch, (c0,c1) packed

// ---------------- complex helpers ----------------
__device__ __forceinline__ float2 cadd(float2 a, float2 b){ return make_float2(a.x+b.x, a.y+b.y); }
__device__ __forceinline__ float2 csub(float2 a, float2 b){ return make_float2(a.x-b.x, a.y-b.y); }
__device__ __forceinline__ float2 cmul(float2 a, float2 b){ return make_float2(a.x*b.x - a.y*b.y, a.x*b.y + a.y*b.x); }

template<bool INV>
__device__ __forceinline__ float2 twg(int e){
    float2 t = d_tw[e & 1023];
    if (INV) t.y = -t.y;
    return t;
}

// =================== block-cooperative radix-4 Stockham FFT, single stream ===================
template<bool INV>
__device__ __forceinline__ void fft1024(float2 a[4],
                                        float* s0re, float* s0im,
                                        float* s1re, float* s1im, int u){
    #pragma unroll
    for (int t = 0; t < 5; t++){
        int s = 1 << (2*t);
        int q = u & (s - 1);
        int e = u - q;
        float2 b0 = cadd(a[0], a[2]);
        float2 b1 = csub(a[0], a[2]);
        float2 b2 = cadd(a[1], a[3]);
        float2 b3 = csub(a[1], a[3]);
        float2 jb3 = INV ? make_float2(-b3.y, b3.x) : make_float2(b3.y, -b3.x);
        float2 c0 = cadd(b0, b2);
        float2 c1 = cmul(cadd(b1, jb3), twg<INV>(e));
        float2 c2 = cmul(csub(b0, b2), twg<INV>(2*e));
        float2 c3 = cmul(csub(b1, jb3), twg<INV>(3*e));
        if (t < 4){
            float* wre = (t & 1) ? s1re : s0re;
            float* wim = (t & 1) ? s1im : s0im;
            int base = 4*u - 3*q;
            wre[swz(t, base      )] = c0.x;  wim[swz(t, base      )] = c0.y;
            wre[swz(t, base +   s)] = c1.x;  wim[swz(t, base +   s)] = c1.y;
            wre[swz(t, base + 2*s)] = c2.x;  wim[swz(t, base + 2*s)] = c2.y;
            wre[swz(t, base + 3*s)] = c3.x;  wim[swz(t, base + 3*s)] = c3.y;
            __syncthreads();
            #pragma unroll
            for (int c = 0; c < 4; c++){
                int idx = swz(t, u + 256*c);
                a[c] = make_float2(wre[idx], wim[idx]);
            }
        } else {
            a[0] = c0; a[1] = c1; a[2] = c2; a[3] = c3;
        }
    }
}

// =================== dual-stream version: two independent FFTs, shared barriers ===================
template<bool INV>
__device__ __forceinline__ void fft1024x2(float2 a[4], float2 b[4],
        float* a0r, float* a0i, float* a1r, float* a1i,
        float* b0r, float* b0i, float* b1r, float* b1i, int u){
    #pragma unroll
    for (int t = 0; t < 5; t++){
        int s = 1 << (2*t);
        int q = u & (s - 1);
        int e = u - q;
        float2 w1 = twg<INV>(e);
        float2 w2 = twg<INV>(2*e);
        float2 w3 = twg<INV>(3*e);
        // stream A
        float2 A0 = cadd(a[0], a[2]);
        float2 A1 = csub(a[0], a[2]);
        float2 A2 = cadd(a[1], a[3]);
        float2 A3 = csub(a[1], a[3]);
        float2 jA3 = INV ? make_float2(-A3.y, A3.x) : make_float2(A3.y, -A3.x);
        float2 ca0 = cadd(A0, A2);
        float2 ca1 = cmul(cadd(A1, jA3), w1);
        float2 ca2 = cmul(csub(A0, A2), w2);
        float2 ca3 = cmul(csub(A1, jA3), w3);
        // stream B
        float2 B0 = cadd(b[0], b[2]);
        float2 B1 = csub(b[0], b[2]);
        float2 B2 = cadd(b[1], b[3]);
        float2 B3 = csub(b[1], b[3]);
        float2 jB3 = INV ? make_float2(-B3.y, B3.x) : make_float2(B3.y, -B3.x);
        float2 cb0 = cadd(B0, B2);
        float2 cb1 = cmul(cadd(B1, jB3), w1);
        float2 cb2 = cmul(csub(B0, B2), w2);
        float2 cb3 = cmul(csub(B1, jB3), w3);
        if (t < 4){
            float* wra = (t & 1) ? a1r : a0r;
            float* wia = (t & 1) ? a1i : a0i;
            float* wrb = (t & 1) ? b1r : b0r;
            float* wib = (t & 1) ? b1i : b0i;
            int base = 4*u - 3*q;
            int i0 = swz(t, base      );
            int i1 = swz(t, base +   s);
            int i2 = swz(t, base + 2*s);
            int i3 = swz(t, base + 3*s);
            wra[i0] = ca0.x;  wia[i0] = ca0.y;
            wra[i1] = ca1.x;  wia[i1] = ca1.y;
            wra[i2] = ca2.x;  wia[i2] = ca2.y;
            wra[i3] = ca3.x;  wia[i3] = ca3.y;
            wrb[i0] = cb0.x;  wib[i0] = cb0.y;
            wrb[i1] = cb1.x;  wib[i1] = cb1.y;
            wrb[i2] = cb2.x;  wib[i2] = cb2.y;
            wrb[i3] = cb3.x;  wib[i3] = cb3.y;
            __syncthreads();
            #pragma unroll
            for (int c = 0; c < 4; c++){
                int idx = swz(t, u + 256*c);
                a[c] = make_float2(wra[idx], wia[idx]);
                b[c] = make_float2(wrb[idx], wib[idx]);
            }
        } else {
            a[0] = ca0; a[1] = ca1; a[2] = ca2; a[3] = ca3;
            b[0] = cb0; b[1] = cb1; b[2] = cb2; b[3] = cb3;
        }
    }
}

// ---------------- kernels ----------------

__global__ void k_init(){
    int i = blockIdx.x * 256 + threadIdx.x;
    if (i < LN){
        double ang = -2.0 * 3.14159265358979323846 * (double)i / 1024.0;
        d_tw[i] = make_float2((float)cos(ang), (float)sin(ang));
        d_sum[i] = 0.f;
        d_sq[i]  = 0.f;
    }
    if (i < NB * LN) d_s[i] = 0.0f;
}

// fused: blocks [0,64) do the channel-sum of x; blocks [64,80) do fft(q)
__global__ void k_sumqf(const float* __restrict__ x, const float* __restrict__ q){
    __shared__ float s0re[SHSZ], s0im[SHSZ], s1re[SHSZ], s1im[SHSZ];
    int u = threadIdx.x;
    if (blockIdx.x < 64){
        int b  = blockIdx.x >> 2;
        int cg = blockIdx.x & 3;
        float acc[4] = {0.f, 0.f, 0.f, 0.f};
        const float* xb = x + ((size_t)b * NC + (size_t)cg * 128) * LN;
        for (int c = 0; c < 128; c++){
            #pragma unroll
            for (int j = 0; j < 4; j++) acc[j] += xb[(size_t)c * LN + u + 256*j];
        }
        #pragma unroll
        for (int j = 0; j < 4; j++) atomicAdd(&d_s[b * LN + u + 256*j], acc[j]);
    } else {
        int b = blockIdx.x - 64;
        float2 a[4];
        #pragma unroll
        for (int j = 0; j < 4; j++) a[j] = make_float2(q[b * LN + u + 256*j], 0.f);
        fft1024<false>(a, s0re, s0im, s1re, s1im, u);
        #pragma unroll
        for (int j = 0; j < 4; j++) d_qf[b * LN + u + 256*j] = a[j];
    }
}

__global__ void k_stats(const float* __restrict__ q,
                        const float* __restrict__ sig,
                        const float* __restrict__ csh){
    __shared__ float s0re[SHSZ], s0im[SHSZ], s1re[SHSZ], s1im[SHSZ];
    __shared__ float gsh[16];
    __shared__ float ssb[LN];
    __shared__ float red[32];
    __shared__ float scal[4];
    int k = blockIdx.x, b = blockIdx.y, u = threadIdx.x;

    float sg = sig[k] + 0.001f;
    float cc = csh[k];
    if (u < 15){
        float t = (float)u - 7.0f - cc;
        gsh[u] = expf(-0.5f * (t / sg) * (t / sg));
    }
    #pragma unroll
    for (int j = 0; j < 4; j++) ssb[u + 256*j] = d_s[b * LN + u + 256*j];
    __syncthreads();

    float gs = 0.f;
    #pragma unroll
    for (int j = 0; j < 15; j++) gs += gsh[j];
    float g[15];
    float ginv = 1.0f / (gs + 0.01f);
    #pragma unroll
    for (int j = 0; j < 15; j++) g[j] = gsh[j] * ginv;

    float2 a[4];
    #pragma unroll
    for (int c = 0; c < 4; c++){
        int l = u + 256*c;
        float bl = 0.f;
        #pragma unroll
        for (int j = 0; j < 15; j++){
            int idx = l + j - 7;
            idx = idx < 0 ? 0 : (idx > LN-1 ? LN-1 : idx);
            bl += ssb[idx] * g[j];
        }
        a[c] = make_float2(bl, 0.f);
    }

    if (u == 0){
        float mxs = 0.f, mys = 0.f;
        for (int bb2 = 0; bb2 < NB; bb2++){
            float bl0 = 0.f;
            #pragma unroll
            for (int j = 0; j < 15; j++){
                int idx = j - 7; if (idx < 0) idx = 0;
                bl0 += d_s[bb2 * LN + idx] * g[j];
            }
            mxs += bl0;
            mys += q[bb2 * LN];
        }
        scal[0] = mxs * (1.0f/16.0f);
        scal[1] = mys * (1.0f/16.0f);
    }
    __syncthreads();

    fft1024<false>(a, s0re, s0im, s1re, s1im, u);

    float2 qf[4];
    #pragma unroll
    for (int c = 0; c < 4; c++) qf[c] = d_qf[b * LN + u + 256*c];

    float mx = scal[0], my = scal[1];

    float v0 = 0.f, v1 = 0.f, v2 = 0.f, v3 = 0.f;
    #pragma unroll
    for (int c = 0; c < 4; c++){
        float2 vm = a[c];  vm.x -= mx;
        float2 t  = cmul(vm, vm);
        v0 += t.x; v1 += t.y;
        float2 qm = qf[c]; qm.x -= mx;
        t = cmul(qm, qm);
        v2 += t.x; v3 += t.y;
    }
    #pragma unroll
    for (int o = 16; o > 0; o >>= 1){
        v0 += __shfl_down_sync(0xffffffffu, v0, o);
        v1 += __shfl_down_sync(0xffffffffu, v1, o);
        v2 += __shfl_down_sync(0xffffffffu, v2, o);
        v3 += __shfl_down_sync(0xffffffffu, v3, o);
    }
    if ((u & 31) == 0){
        int w = u >> 5;
        red[w*4+0] = v0; red[w*4+1] = v1; red[w*4+2] = v2; red[w*4+3] = v3;
    }
    __syncthreads();
    float2 AS = make_float2(0.f, 0.f), BS = make_float2(0.f, 0.f);
    #pragma unroll
    for (int w = 0; w < 8; w++){
        AS.x += red[w*4+0]; AS.y += red[w*4+1];
        BS.x += red[w*4+2]; BS.y += red[w*4+3];
    }
    float2 dd = cmul(AS, BS);
    dd.x += 0.001f;
    float dinv = rsqrtf(dd.x*dd.x + dd.y*dd.y);

    float2 pa[4];
    #pragma unroll
    for (int c = 0; c < 4; c++){
        float2 vm = a[c];  vm.x -= mx;
        float2 qm = qf[c]; qm.x -= my;
        float2 cov = cmul(vm, qm);
        float cm = sqrtf(cov.x*cov.x + cov.y*cov.y);
        float wv = 1.0f - expf(-0.1f * cm * dinv);
        // pre-scale by 1/1024 so k_main's ifft output needs no normalization
        d_w[(b * KN + k) * LN + u + 256*c] = wv * (1.0f/1024.0f);
        float om = 1.0f - wv;
        pa[c] = make_float2(om * qf[c].x, om * qf[c].y);
    }
    __syncthreads();
    fft1024<true>(pa, s0re, s0im, s1re, s1im, u);
    #pragma unroll
    for (int c = 0; c < 4; c++)
        d_p[(b * KN + k) * LN + u + 256*c] = pa[c].x * (1.0f/1024.0f);
}

// -------- main kernel: block per channel pair; two inverse FFTs interleaved --------
// (256,2): cap regs at 128 — the value ptxas chose naturally in R9 (no spills) —
// so the swizzle's extra index values get rematerialized instead of costing a block.
__global__ void __launch_bounds__(256, 2) k_main(const float* __restrict__ x){
    __shared__ float A0r[SHSZ], A0i[SHSZ], A1r[SHSZ], A1i[SHSZ];
    __shared__ float B0r[SHSZ], B0i[SHSZ], B1r[SHSZ], B1i[SHSZ];
    int cp = blockIdx.x;
    int b  = blockIdx.y;
    int u  = threadIdx.x;
    const float* x0 = x + ((size_t)b * NC + 2*cp    ) * LN;
    const float* x1 = x + ((size_t)b * NC + 2*cp + 1) * LN;

    float xa[4], xb[4];
    float2 z[4];
    #pragma unroll
    for (int j = 0; j < 4; j++){
        xa[j] = x0[u + 256*j];
        xb[j] = x1[u + 256*j];
        z[j] = make_float2(xa[j], xb[j]);
    }
    fft1024<false>(z, A0r, A0i, A1r, A1i, u);   // Z = X0 + i*X1

    float sm[4] = {0,0,0,0}, sq[4] = {0,0,0,0};
    __half2* ob = d_o + ((size_t)(b * NCP + cp)) * KN * LN;
    const float* wb = d_w + (size_t)b * KN * LN;
    const float* pb = d_p + (size_t)b * KN * LN;

    for (int k = 0; k < KN; k += 2){
        float2 a[4], bb[4];
        #pragma unroll
        for (int j = 0; j < 4; j++){
            int l = u + 256*j;
            float wv0 = wb[ k      * LN + l];
            float wv1 = wb[(k + 1) * LN + l];
            a[j]  = make_float2(z[j].x * wv0, z[j].y * wv0);
            bb[j] = make_float2(z[j].x * wv1, z[j].y * wv1);
        }
        fft1024x2<true>(a, bb, A0r, A0i, A1r, A1i, B0r, B0i, B1r, B1i, u);
        #pragma unroll
        for (int j = 0; j < 4; j++){
            int l = u + 256*j;
            float pp0 = pb[ k      * LN + l];
            float pp1 = pb[(k + 1) * LN + l];
            float o0 = fabsf(a[j].x  + pp0) + xa[j];   // w pre-scaled by 1/1024
            float o1 = fabsf(a[j].y  + pp0) + xb[j];
            float o2 = fabsf(bb[j].x + pp1) + xa[j];
            float o3 = fabsf(bb[j].y + pp1) + xb[j];
            ob[ k      * LN + l] = __floats2half2_rn(o0, o1);
            ob[(k + 1) * LN + l] = __floats2half2_rn(o2, o3);
            sm[j] += (o0 + o1) + (o2 + o3);
            sq[j] += (o0*o0 + o1*o1) + (o2*o2 + o3*o3);
        }
        // no trailing barrier needed: stage-3 barrier of this call separates the
        // last reads of buffer set 0 from the next iteration's stage-0 writes.
    }
    #pragma unroll
    for (int j = 0; j < 4; j++){
        atomicAdd(&d_sum[u + 256*j], sm[j]);
        atomicAdd(&d_sq[u + 256*j],  sq[j]);
    }
}

__global__ void k_bn(const float* __restrict__ gamma, const float* __restrict__ beta){
    int l = blockIdx.x * 256 + threadIdx.x;
    if (l < LN){
        float cnt  = (float)(NB * NC * KN);   // 65536
        float mean = d_sum[l] / cnt;
        float var  = d_sq[l] / cnt - mean * mean;
        float sc = gamma[l] * rsqrtf(var + 1e-5f);
        d_scale[l] = sc;
        d_shift[l] = beta[l] - mean * sc;
    }
}

__global__ void __launch_bounds__(256) k_attn(const float* __restrict__ q, float* __restrict__ out){
    __shared__ float red[8 * 16];
    int cp = blockIdx.x, b = blockIdx.y, u = threadIdx.x;
    const __half2* ob = d_o + ((size_t)(b * NCP + cp)) * KN * LN;

    float qa[4], sc[4], sh[4];
    #pragma unroll
    for (int j = 0; j < 4; j++){
        int l = u + 256*j;
        float sl = d_scale[l];
        qa[j] = q[b * LN + l] * sl;
        sc[j] = sl;
        sh[j] = d_shift[l];
    }
    __half2 ov[KN][4];
    float s0[KN], s1[KN];
    #pragma unroll
    for (int k = 0; k < KN; k++){ s0[k] = 0.f; s1[k] = 0.f; }
    #pragma unroll
    for (int k = 0; k < KN; k++){
        #pragma unroll
        for (int j = 0; j < 4; j++){
            __half2 h = ob[k * LN + u + 256*j];
            ov[k][j] = h;
            float2 f = __half22float2(h);
            s0[k] += qa[j] * f.x;
            s1[k] += qa[j] * f.y;
        }
    }
    #pragma unroll
    for (int k = 0; k < KN; k++){
        #pragma unroll
        for (int o = 16; o > 0; o >>= 1){
            s0[k] += __shfl_down_sync(0xffffffffu, s0[k], o);
            s1[k] += __shfl_down_sync(0xffffffffu, s1[k], o);
        }
    }
    if ((u & 31) == 0){
        int w = u >> 5;
        #pragma unroll
        for (int k = 0; k < KN; k++){
            red[w * 16 + k]     = s0[k];
            red[w * 16 + 8 + k] = s1[k];
        }
    }
    __syncthreads();
    float t0[KN], t1[KN];
    #pragma unroll
    for (int k = 0; k < KN; k++){
        float a0 = 0.f, a1 = 0.f;
        #pragma unroll
        for (int w = 0; w < 8; w++){
            a0 += red[w * 16 + k];
            a1 += red[w * 16 + 8 + k];
        }
        t0[k] = a0; t1[k] = a1;
    }
    float m0 = t0[0], m1 = t1[0];
    #pragma unroll
    for (int k = 1; k < KN; k++){ m0 = fmaxf(m0, t0[k]); m1 = fmaxf(m1, t1[k]); }
    float a0[KN], a1[KN], se0 = 0.f, se1 = 0.f;
    #pragma unroll
    for (int k = 0; k < KN; k++){
        a0[k] = expf(t0[k] - m0); se0 += a0[k];
        a1[k] = expf(t1[k] - m1); se1 += a1[k];
    }
    float i0 = 1.0f / se0, i1 = 1.0f / se1;
    float* o0p = out + ((size_t)b * NC + 2*cp    ) * LN;
    float* o1p = out + ((size_t)b * NC + 2*cp + 1) * LN;
    #pragma unroll
    for (int j = 0; j < 4; j++){
        float acc0 = 0.f, acc1 = 0.f;
        #pragma unroll
        for (int k = 0; k < KN; k++){
            float2 f = __half22float2(ov[k][j]);
            acc0 += a0[k] * f.x;
            acc1 += a1[k] * f.y;
        }
        int l = u + 256*j;
        o0p[l] = sc[j] * (acc0 * i0) + sh[j];
        o1p[l] = sc[j] * (acc1 * i1) + sh[j];
    }
}

extern "C" void kernel_launch(void* const* d_in, const int* in_sizes, int n_in,
                              void* d_out, int out_size){
    const float* x     = (const float*)d_in[0];
    const float* q     = (const float*)d_in[1];
    const float* sig   = (const float*)d_in[2];
    const float* csh   = (const float*)d_in[3];
    const float* gamma = (const float*)d_in[4];
    const float* beta  = (const float*)d_in[5];
    float* out = (float*)d_out;

    k_init <<<64, 256>>>();
    k_sumqf<<<80, 256>>>(x, q);
    k_stats<<<dim3(KN, NB), 256>>>(q, sig, csh);
    k_main <<<dim3(NCP, NB), 256>>>(x);
    k_bn   <<<4, 256>>>(gamma, beta);
    k_attn <<<dim3(NCP, NB), 256>>>(q, out);
}

// round 12
// speedup vs baseline: 1.3433x; 1.0164x over previous
#include <cuda_runtime.h>
#include <cuda_fp16.h>

#define LN 1024
#define NB 16
#define NC 512
#define KN 8
#define NCP (NC/2)

// per-stage conflict-free swizzle for COMPLEX (8-byte) shared elements, banks mod 16:
//  t=0: XOR a-bits into bits {0,1,3}    t=1: XOR a-bits into bits {2,3,0}
//  t=2,3: identity (stores are naturally 2-per-class mod 16)
// t is compile-time after unrolling -> branches fold.
__device__ __forceinline__ int cswz(int t, int i){
    if (t == 0) return i ^ (((i >> 4) & 3) | (((i >> 6) & 1) << 3));
    if (t == 1) return i ^ ((((i >> 4) & 3) << 2) | ((i >> 6) & 1));
    return i;
}

// ---------------- device scratch (statically allocated; no runtime allocs) ----------------
__device__ float2  d_tw[LN];                 // forward twiddles e^{-2pi i j/1024}
__device__ float   d_s[NB * LN];             // channel-sum of x
__device__ float2  d_qf[NB * LN];            // fft(q)
__device__ float   d_w[NB * KN * LN];        // blend weights, PRE-SCALED by 1/1024
__device__ float   d_p[NB * KN * LN];        // P = ifft((1-w)*qfft).real
__device__ float   d_sum[LN];                // BN sum per l
__device__ float   d_sq[LN];                 // BN sumsq per l
__device__ float   d_scale[LN];
__device__ float   d_shift[LN];
__device__ __half2 d_o[(size_t)NB * NCP * KN * LN];   // 128 MB o scratch, (c0,c1) packed

// ---------------- complex helpers ----------------
__device__ __forceinline__ float2 cadd(float2 a, float2 b){ return make_float2(a.x+b.x, a.y+b.y); }
__device__ __forceinline__ float2 csub(float2 a, float2 b){ return make_float2(a.x-b.x, a.y-b.y); }
__device__ __forceinline__ float2 cmul(float2 a, float2 b){ return make_float2(a.x*b.x - a.y*b.y, a.x*b.y + a.y*b.x); }

template<bool INV>
__device__ __forceinline__ float2 twg(int e){
    float2 t = d_tw[e & 1023];
    if (INV) t.y = -t.y;
    return t;
}

// =================== block-cooperative radix-4 Stockham FFT, single stream ===================
// 256 threads, 4 pts/thread, float2 (complex) shared buffers, 1 barrier per exchange.
template<bool INV>
__device__ __forceinline__ void fft1024(float2 a[4], float2* s0, float2* s1, int u){
    #pragma unroll
    for (int t = 0; t < 5; t++){
        int s = 1 << (2*t);
        int q = u & (s - 1);
        int e = u - q;
        float2 b0 = cadd(a[0], a[2]);
        float2 b1 = csub(a[0], a[2]);
        float2 b2 = cadd(a[1], a[3]);
        float2 b3 = csub(a[1], a[3]);
        float2 jb3 = INV ? make_float2(-b3.y, b3.x) : make_float2(b3.y, -b3.x);
        float2 c0 = cadd(b0, b2);
        float2 c1 = cmul(cadd(b1, jb3), twg<INV>(e));
        float2 c2 = cmul(csub(b0, b2), twg<INV>(2*e));
        float2 c3 = cmul(csub(b1, jb3), twg<INV>(3*e));
        if (t < 4){
            float2* ws = (t & 1) ? s1 : s0;
            int base = 4*u - 3*q;
            ws[cswz(t, base      )] = c0;
            ws[cswz(t, base +   s)] = c1;
            ws[cswz(t, base + 2*s)] = c2;
            ws[cswz(t, base + 3*s)] = c3;
            __syncthreads();
            #pragma unroll
            for (int c = 0; c < 4; c++)
                a[c] = ws[cswz(t, u + 256*c)];
        } else {
            a[0] = c0; a[1] = c1; a[2] = c2; a[3] = c3;
        }
    }
}

// =================== dual-stream version: two independent FFTs, shared barriers ===================
template<bool INV>
__device__ __forceinline__ void fft1024x2(float2 a[4], float2 b[4],
        float2* sA0, float2* sA1, float2* sB0, float2* sB1, int u){
    #pragma unroll
    for (int t = 0; t < 5; t++){
        int s = 1 << (2*t);
        int q = u & (s - 1);
        int e = u - q;
        float2 w1 = twg<INV>(e);
        float2 w2 = twg<INV>(2*e);
        float2 w3 = twg<INV>(3*e);
        // stream A
        float2 A0 = cadd(a[0], a[2]);
        float2 A1 = csub(a[0], a[2]);
        float2 A2 = cadd(a[1], a[3]);
        float2 A3 = csub(a[1], a[3]);
        float2 jA3 = INV ? make_float2(-A3.y, A3.x) : make_float2(A3.y, -A3.x);
        float2 ca0 = cadd(A0, A2);
        float2 ca1 = cmul(cadd(A1, jA3), w1);
        float2 ca2 = cmul(csub(A0, A2), w2);
        float2 ca3 = cmul(csub(A1, jA3), w3);
        // stream B
        float2 B0 = cadd(b[0], b[2]);
        float2 B1 = csub(b[0], b[2]);
        float2 B2 = cadd(b[1], b[3]);
        float2 B3 = csub(b[1], b[3]);
        float2 jB3 = INV ? make_float2(-B3.y, B3.x) : make_float2(B3.y, -B3.x);
        float2 cb0 = cadd(B0, B2);
        float2 cb1 = cmul(cadd(B1, jB3), w1);
        float2 cb2 = cmul(csub(B0, B2), w2);
        float2 cb3 = cmul(csub(B1, jB3), w3);
        if (t < 4){
            float2* wa = (t & 1) ? sA1 : sA0;
            float2* wb = (t & 1) ? sB1 : sB0;
            int base = 4*u - 3*q;
            int i0 = cswz(t, base      );
            int i1 = cswz(t, base +   s);
            int i2 = cswz(t, base + 2*s);
            int i3 = cswz(t, base + 3*s);
            wa[i0] = ca0;  wa[i1] = ca1;  wa[i2] = ca2;  wa[i3] = ca3;
            wb[i0] = cb0;  wb[i1] = cb1;  wb[i2] = cb2;  wb[i3] = cb3;
            __syncthreads();
            #pragma unroll
            for (int c = 0; c < 4; c++){
                int idx = cswz(t, u + 256*c);
                a[c] = wa[idx];
                b[c] = wb[idx];
            }
        } else {
            a[0] = ca0; a[1] = ca1; a[2] = ca2; a[3] = ca3;
            b[0] = cb0; b[1] = cb1; b[2] = cb2; b[3] = cb3;
        }
    }
}

// ---------------- kernels ----------------

__global__ void k_init(){
    int i = blockIdx.x * 256 + threadIdx.x;
    if (i < LN){
        double ang = -2.0 * 3.14159265358979323846 * (double)i / 1024.0;
        d_tw[i] = make_float2((float)cos(ang), (float)sin(ang));
        d_sum[i] = 0.f;
        d_sq[i]  = 0.f;
    }
    if (i < NB * LN) d_s[i] = 0.0f;
}

// fused: blocks [0,64) do the channel-sum of x; blocks [64,80) do fft(q)
__global__ void k_sumqf(const float* __restrict__ x, const float* __restrict__ q){
    __shared__ float2 S0[LN], S1[LN];
    int u = threadIdx.x;
    if (blockIdx.x < 64){
        int b  = blockIdx.x >> 2;
        int cg = blockIdx.x & 3;
        float acc[4] = {0.f, 0.f, 0.f, 0.f};
        const float* xb = x + ((size_t)b * NC + (size_t)cg * 128) * LN;
        for (int c = 0; c < 128; c++){
            #pragma unroll
            for (int j = 0; j < 4; j++) acc[j] += xb[(size_t)c * LN + u + 256*j];
        }
        #pragma unroll
        for (int j = 0; j < 4; j++) atomicAdd(&d_s[b * LN + u + 256*j], acc[j]);
    } else {
        int b = blockIdx.x - 64;
        float2 a[4];
        #pragma unroll
        for (int j = 0; j < 4; j++) a[j] = make_float2(q[b * LN + u + 256*j], 0.f);
        fft1024<false>(a, S0, S1, u);
        #pragma unroll
        for (int j = 0; j < 4; j++) d_qf[b * LN + u + 256*j] = a[j];
    }
}

__global__ void k_stats(const float* __restrict__ q,
                        const float* __restrict__ sig,
                        const float* __restrict__ csh){
    __shared__ float2 S0[LN], S1[LN];
    __shared__ float gsh[16];
    __shared__ float ssb[LN];
    __shared__ float red[32];
    __shared__ float scal[4];
    int k = blockIdx.x, b = blockIdx.y, u = threadIdx.x;

    float sg = sig[k] + 0.001f;
    float cc = csh[k];
    if (u < 15){
        float t = (float)u - 7.0f - cc;
        gsh[u] = expf(-0.5f * (t / sg) * (t / sg));
    }
    #pragma unroll
    for (int j = 0; j < 4; j++) ssb[u + 256*j] = d_s[b * LN + u + 256*j];
    __syncthreads();

    float gs = 0.f;
    #pragma unroll
    for (int j = 0; j < 15; j++) gs += gsh[j];
    float g[15];
    float ginv = 1.0f / (gs + 0.01f);
    #pragma unroll
    for (int j = 0; j < 15; j++) g[j] = gsh[j] * ginv;

    float2 a[4];
    #pragma unroll
    for (int c = 0; c < 4; c++){
        int l = u + 256*c;
        float bl = 0.f;
        #pragma unroll
        for (int j = 0; j < 15; j++){
            int idx = l + j - 7;
            idx = idx < 0 ? 0 : (idx > LN-1 ? LN-1 : idx);
            bl += ssb[idx] * g[j];
        }
        a[c] = make_float2(bl, 0.f);
    }

    if (u == 0){
        float mxs = 0.f, mys = 0.f;
        for (int bb2 = 0; bb2 < NB; bb2++){
            float bl0 = 0.f;
            #pragma unroll
            for (int j = 0; j < 15; j++){
                int idx = j - 7; if (idx < 0) idx = 0;
                bl0 += d_s[bb2 * LN + idx] * g[j];
            }
            mxs += bl0;
            mys += q[bb2 * LN];
        }
        scal[0] = mxs * (1.0f/16.0f);
        scal[1] = mys * (1.0f/16.0f);
    }
    __syncthreads();

    fft1024<false>(a, S0, S1, u);

    float2 qf[4];
    #pragma unroll
    for (int c = 0; c < 4; c++) qf[c] = d_qf[b * LN + u + 256*c];

    float mx = scal[0], my = scal[1];

    float v0 = 0.f, v1 = 0.f, v2 = 0.f, v3 = 0.f;
    #pragma unroll
    for (int c = 0; c < 4; c++){
        float2 vm = a[c];  vm.x -= mx;
        float2 t  = cmul(vm, vm);
        v0 += t.x; v1 += t.y;
        float2 qm = qf[c]; qm.x -= mx;
        t = cmul(qm, qm);
        v2 += t.x; v3 += t.y;
    }
    #pragma unroll
    for (int o = 16; o > 0; o >>= 1){
        v0 += __shfl_down_sync(0xffffffffu, v0, o);
        v1 += __shfl_down_sync(0xffffffffu, v1, o);
        v2 += __shfl_down_sync(0xffffffffu, v2, o);
        v3 += __shfl_down_sync(0xffffffffu, v3, o);
    }
    if ((u & 31) == 0){
        int w = u >> 5;
        red[w*4+0] = v0; red[w*4+1] = v1; red[w*4+2] = v2; red[w*4+3] = v3;
    }
    __syncthreads();
    float2 AS = make_float2(0.f, 0.f), BS = make_float2(0.f, 0.f);
    #pragma unroll
    for (int w = 0; w < 8; w++){
        AS.x += red[w*4+0]; AS.y += red[w*4+1];
        BS.x += red[w*4+2]; BS.y += red[w*4+3];
    }
    float2 dd = cmul(AS, BS);
    dd.x += 0.001f;
    float dinv = rsqrtf(dd.x*dd.x + dd.y*dd.y);

    float2 pa[4];
    #pragma unroll
    for (int c = 0; c < 4; c++){
        float2 vm = a[c];  vm.x -= mx;
        float2 qm = qf[c]; qm.x -= my;
        float2 cov = cmul(vm, qm);
        float cm = sqrtf(cov.x*cov.x + cov.y*cov.y);
        float wv = 1.0f - expf(-0.1f * cm * dinv);
        // pre-scale by 1/1024 so k_main's ifft output needs no normalization
        d_w[(b * KN + k) * LN + u + 256*c] = wv * (1.0f/1024.0f);
        float om = 1.0f - wv;
        pa[c] = make_float2(om * qf[c].x, om * qf[c].y);
    }
    __syncthreads();
    fft1024<true>(pa, S0, S1, u);
    #pragma unroll
    for (int c = 0; c < 4; c++)
        d_p[(b * KN + k) * LN + u + 256*c] = pa[c].x * (1.0f/1024.0f);
}

// -------- main kernel: block per channel pair; two inverse FFTs interleaved --------
// (256,2): regs capped at 128 (R9's natural no-spill value).
__global__ void __launch_bounds__(256, 2) k_main(const float* __restrict__ x){
    __shared__ float2 SA0[LN], SA1[LN], SB0[LN], SB1[LN];   // 32 KB
    int cp = blockIdx.x;
    int b  = blockIdx.y;
    int u  = threadIdx.x;
    const float* x0 = x + ((size_t)b * NC + 2*cp    ) * LN;
    const float* x1 = x + ((size_t)b * NC + 2*cp + 1) * LN;

    float xa[4], xb[4];
    float2 z[4];
    #pragma unroll
    for (int j = 0; j < 4; j++){
        xa[j] = x0[u + 256*j];
        xb[j] = x1[u + 256*j];
        z[j] = make_float2(xa[j], xb[j]);
    }
    fft1024<false>(z, SA0, SA1, u);   // Z = X0 + i*X1

    float sm[4] = {0,0,0,0}, sq[4] = {0,0,0,0};
    __half2* ob = d_o + ((size_t)(b * NCP + cp)) * KN * LN;
    const float* wb = d_w + (size_t)b * KN * LN;
    const float* pb = d_p + (size_t)b * KN * LN;

    for (int k = 0; k < KN; k += 2){
        float2 a[4], bb[4];
        #pragma unroll
        for (int j = 0; j < 4; j++){
            int l = u + 256*j;
            float wv0 = wb[ k      * LN + l];
            float wv1 = wb[(k + 1) * LN + l];
            a[j]  = make_float2(z[j].x * wv0, z[j].y * wv0);
            bb[j] = make_float2(z[j].x * wv1, z[j].y * wv1);
        }
        fft1024x2<true>(a, bb, SA0, SA1, SB0, SB1, u);
        #pragma unroll
        for (int j = 0; j < 4; j++){
            int l = u + 256*j;
            float pp0 = pb[ k      * LN + l];
            float pp1 = pb[(k + 1) * LN + l];
            float o0 = fabsf(a[j].x  + pp0) + xa[j];   // w pre-scaled by 1/1024
            float o1 = fabsf(a[j].y  + pp0) + xb[j];
            float o2 = fabsf(bb[j].x + pp1) + xa[j];
            float o3 = fabsf(bb[j].y + pp1) + xb[j];
            ob[ k      * LN + l] = __floats2half2_rn(o0, o1);
            ob[(k + 1) * LN + l] = __floats2half2_rn(o2, o3);
            sm[j] += (o0 + o1) + (o2 + o3);
            sq[j] += (o0*o0 + o1*o1) + (o2*o2 + o3*o3);
        }
        // no trailing barrier needed: stage-3 barrier of this call separates the
        // last reads of buffer set 0 from the next iteration's stage-0 writes.
    }
    #pragma unroll
    for (int j = 0; j < 4; j++){
        atomicAdd(&d_sum[u + 256*j], sm[j]);
        atomicAdd(&d_sq[u + 256*j],  sq[j]);
    }
}

__global__ void k_bn(const float* __restrict__ gamma, const float* __restrict__ beta){
    int l = blockIdx.x * 256 + threadIdx.x;
    if (l < LN){
        float cnt  = (float)(NB * NC * KN);   // 65536
        float mean = d_sum[l] / cnt;
        float var  = d_sq[l] / cnt - mean * mean;
        float sc = gamma[l] * rsqrtf(var + 1e-5f);
        d_scale[l] = sc;
        d_shift[l] = beta[l] - mean * sc;
    }
}

__global__ void __launch_bounds__(256) k_attn(const float* __restrict__ q, float* __restrict__ out){
    __shared__ float red[8 * 16];
    int cp = blockIdx.x, b = blockIdx.y, u = threadIdx.x;
    const __half2* ob = d_o + ((size_t)(b * NCP + cp)) * KN * LN;

    float qa[4], sc[4], sh[4];
    #pragma unroll
    for (int j = 0; j < 4; j++){
        int l = u + 256*j;
        float sl = d_scale[l];
        qa[j] = q[b * LN + l] * sl;
        sc[j] = sl;
        sh[j] = d_shift[l];
    }
    __half2 ov[KN][4];
    float s0[KN], s1[KN];
    #pragma unroll
    for (int k = 0; k < KN; k++){ s0[k] = 0.f; s1[k] = 0.f; }
    #pragma unroll
    for (int k = 0; k < KN; k++){
        #pragma unroll
        for (int j = 0; j < 4; j++){
            __half2 h = ob[k * LN + u + 256*j];
            ov[k][j] = h;
            float2 f = __half22float2(h);
            s0[k] += qa[j] * f.x;
            s1[k] += qa[j] * f.y;
        }
    }
    #pragma unroll
    for (int k = 0; k < KN; k++){
        #pragma unroll
        for (int o = 16; o > 0; o >>= 1){
            s0[k] += __shfl_down_sync(0xffffffffu, s0[k], o);
            s1[k] += __shfl_down_sync(0xffffffffu, s1[k], o);
        }
    }
    if ((u & 31) == 0){
        int w = u >> 5;
        #pragma unroll
        for (int k = 0; k < KN; k++){
            red[w * 16 + k]     = s0[k];
            red[w * 16 + 8 + k] = s1[k];
        }
    }
    __syncthreads();
    float t0[KN], t1[KN];
    #pragma unroll
    for (int k = 0; k < KN; k++){
        float a0 = 0.f, a1 = 0.f;
        #pragma unroll
        for (int w = 0; w < 8; w++){
            a0 += red[w * 16 + k];
            a1 += red[w * 16 + 8 + k];
        }
        t0[k] = a0; t1[k] = a1;
    }
    float m0 = t0[0], m1 = t1[0];
    #pragma unroll
    for (int k = 1; k < KN; k++){ m0 = fmaxf(m0, t0[k]); m1 = fmaxf(m1, t1[k]); }
    float a0[KN], a1[KN], se0 = 0.f, se1 = 0.f;
    #pragma unroll
    for (int k = 0; k < KN; k++){
        a0[k] = expf(t0[k] - m0); se0 += a0[k];
        a1[k] = expf(t1[k] - m1); se1 += a1[k];
    }
    float i0 = 1.0f / se0, i1 = 1.0f / se1;
    float* o0p = out + ((size_t)b * NC + 2*cp    ) * LN;
    float* o1p = out + ((size_t)b * NC + 2*cp + 1) * LN;
    #pragma unroll
    for (int j = 0; j < 4; j++){
        float acc0 = 0.f, acc1 = 0.f;
        #pragma unroll
        for (int k = 0; k < KN; k++){
            float2 f = __half22float2(ov[k][j]);
            acc0 += a0[k] * f.x;
            acc1 += a1[k] * f.y;
        }
        int l = u + 256*j;
        o0p[l] = sc[j] * (acc0 * i0) + sh[j];
        o1p[l] = sc[j] * (acc1 * i1) + sh[j];
    }
}

extern "C" void kernel_launch(void* const* d_in, const int* in_sizes, int n_in,
                              void* d_out, int out_size){
    const float* x     = (const float*)d_in[0];
    const float* q     = (const float*)d_in[1];
    const float* sig   = (const float*)d_in[2];
    const float* csh   = (const float*)d_in[3];
    const float* gamma = (const float*)d_in[4];
    const float* beta  = (const float*)d_in[5];
    float* out = (float*)d_out;

    k_init <<<64, 256>>>();
    k_sumqf<<<80, 256>>>(x, q);
    k_stats<<<dim3(KN, NB), 256>>>(q, sig, csh);
    k_main <<<dim3(NCP, NB), 256>>>(x);
    k_bn   <<<4, 256>>>(gamma, beta);
    k_attn <<<dim3(NCP, NB), 256>>>(q, out);
}

// round 13
// speedup vs baseline: 1.3634x; 1.0150x over previous
#include <cuda_runtime.h>
#include <cuda_fp16.h>

#define LN 1024
#define NB 16
#define NC 512
#define KN 8
#define NCP (NC/2)

// ---- swizzle for 8-byte (float2) shared elements, banks mod 16 (single-stream FFT) ----
__device__ __forceinline__ int cswz(int t, int i){
    if (t == 0) return i ^ (((i >> 4) & 3) | (((i >> 6) & 1) << 3));
    if (t == 1) return i ^ ((((i >> 4) & 3) << 2) | ((i >> 6) & 1));
    return i;
}

// ---- swizzle for 16-byte (float4) shared elements, classes mod 8 (dual-stream FFT) ----
//  t=0: XOR bits3-4 into bits0-1     t=1: XOR bit4 into bit2     t=2,3: identity
__device__ __forceinline__ int swz4(int t, int i){
    if (t == 0) return i ^ ((i >> 3) & 3);
    if (t == 1) return i ^ (((i >> 4) & 1) << 2);
    return i;
}

// ---------------- device scratch (statically allocated; no runtime allocs) ----------------
__device__ float2  d_tw[LN];                 // forward twiddles e^{-2pi i j/1024}
__device__ float   d_s[NB * LN];             // channel-sum of x
__device__ float2  d_qf[NB * LN];            // fft(q)
__device__ float   d_w[NB * KN * LN];        // blend weights, PRE-SCALED by 1/1024
__device__ float   d_p[NB * KN * LN];        // P = ifft((1-w)*qfft).real
__device__ float   d_sum[LN];                // BN sum per l
__device__ float   d_sq[LN];                 // BN sumsq per l
__device__ float   d_scale[LN];
__device__ float   d_shift[LN];
__device__ __half2 d_o[(size_t)NB * NCP * KN * LN];   // 128 MB o scratch, (c0,c1) packed

// ---------------- complex helpers ----------------
__device__ __forceinline__ float2 cadd(float2 a, float2 b){ return make_float2(a.x+b.x, a.y+b.y); }
__device__ __forceinline__ float2 csub(float2 a, float2 b){ return make_float2(a.x-b.x, a.y-b.y); }
__device__ __forceinline__ float2 cmul(float2 a, float2 b){ return make_float2(a.x*b.x - a.y*b.y, a.x*b.y + a.y*b.x); }

template<bool INV>
__device__ __forceinline__ float2 twg(int e){
    float2 t = d_tw[e & 1023];
    if (INV) t.y = -t.y;
    return t;
}

// =================== block-cooperative radix-4 Stockham FFT, single stream ===================
template<bool INV>
__device__ __forceinline__ void fft1024(float2 a[4], float2* s0, float2* s1, int u){
    #pragma unroll
    for (int t = 0; t < 5; t++){
        int s = 1 << (2*t);
        int q = u & (s - 1);
        int e = u - q;
        float2 b0 = cadd(a[0], a[2]);
        float2 b1 = csub(a[0], a[2]);
        float2 b2 = cadd(a[1], a[3]);
        float2 b3 = csub(a[1], a[3]);
        float2 jb3 = INV ? make_float2(-b3.y, b3.x) : make_float2(b3.y, -b3.x);
        float2 c0 = cadd(b0, b2);
        float2 c1 = cmul(cadd(b1, jb3), twg<INV>(e));
        float2 c2 = cmul(csub(b0, b2), twg<INV>(2*e));
        float2 c3 = cmul(csub(b1, jb3), twg<INV>(3*e));
        if (t < 4){
            float2* ws = (t & 1) ? s1 : s0;
            int base = 4*u - 3*q;
            ws[cswz(t, base      )] = c0;
            ws[cswz(t, base +   s)] = c1;
            ws[cswz(t, base + 2*s)] = c2;
            ws[cswz(t, base + 3*s)] = c3;
            __syncthreads();
            #pragma unroll
            for (int c = 0; c < 4; c++)
                a[c] = ws[cswz(t, u + 256*c)];
        } else {
            a[0] = c0; a[1] = c1; a[2] = c2; a[3] = c3;
        }
    }
}

// =================== dual-stream FFT: A/B packed into float4 shared elements ===================
template<bool INV>
__device__ __forceinline__ void fft1024x2(float2 a[4], float2 b[4],
                                          float4* s0, float4* s1, int u){
    #pragma unroll
    for (int t = 0; t < 5; t++){
        int s = 1 << (2*t);
        int q = u & (s - 1);
        int e = u - q;
        float2 w1 = twg<INV>(e);
        float2 w2 = twg<INV>(2*e);
        float2 w3 = twg<INV>(3*e);
        // stream A
        float2 A0 = cadd(a[0], a[2]);
        float2 A1 = csub(a[0], a[2]);
        float2 A2 = cadd(a[1], a[3]);
        float2 A3 = csub(a[1], a[3]);
        float2 jA3 = INV ? make_float2(-A3.y, A3.x) : make_float2(A3.y, -A3.x);
        float2 ca0 = cadd(A0, A2);
        float2 ca1 = cmul(cadd(A1, jA3), w1);
        float2 ca2 = cmul(csub(A0, A2), w2);
        float2 ca3 = cmul(csub(A1, jA3), w3);
        // stream B
        float2 B0 = cadd(b[0], b[2]);
        float2 B1 = csub(b[0], b[2]);
        float2 B2 = cadd(b[1], b[3]);
        float2 B3 = csub(b[1], b[3]);
        float2 jB3 = INV ? make_float2(-B3.y, B3.x) : make_float2(B3.y, -B3.x);
        float2 cb0 = cadd(B0, B2);
        float2 cb1 = cmul(cadd(B1, jB3), w1);
        float2 cb2 = cmul(csub(B0, B2), w2);
        float2 cb3 = cmul(csub(B1, jB3), w3);
        if (t < 4){
            float4* ws = (t & 1) ? s1 : s0;
            int base = 4*u - 3*q;
            ws[swz4(t, base      )] = make_float4(ca0.x, ca0.y, cb0.x, cb0.y);
            ws[swz4(t, base +   s)] = make_float4(ca1.x, ca1.y, cb1.x, cb1.y);
            ws[swz4(t, base + 2*s)] = make_float4(ca2.x, ca2.y, cb2.x, cb2.y);
            ws[swz4(t, base + 3*s)] = make_float4(ca3.x, ca3.y, cb3.x, cb3.y);
            __syncthreads();
            #pragma unroll
            for (int c = 0; c < 4; c++){
                float4 v = ws[swz4(t, u + 256*c)];
                a[c] = make_float2(v.x, v.y);
                b[c] = make_float2(v.z, v.w);
            }
        } else {
            a[0] = ca0; a[1] = ca1; a[2] = ca2; a[3] = ca3;
            b[0] = cb0; b[1] = cb1; b[2] = cb2; b[3] = cb3;
        }
    }
}

// ---------------- kernels ----------------

__global__ void k_init(){
    int i = blockIdx.x * 256 + threadIdx.x;
    if (i < LN){
        double ang = -2.0 * 3.14159265358979323846 * (double)i / 1024.0;
        d_tw[i] = make_float2((float)cos(ang), (float)sin(ang));
        d_sum[i] = 0.f;
        d_sq[i]  = 0.f;
    }
    if (i < NB * LN) d_s[i] = 0.0f;
}

// fused: blocks [0,64) do the channel-sum of x; blocks [64,80) do fft(q)
__global__ void k_sumqf(const float* __restrict__ x, const float* __restrict__ q){
    __shared__ float2 S0[LN], S1[LN];
    int u = threadIdx.x;
    if (blockIdx.x < 64){
        int b  = blockIdx.x >> 2;
        int cg = blockIdx.x & 3;
        float acc[4] = {0.f, 0.f, 0.f, 0.f};
        const float* xb = x + ((size_t)b * NC + (size_t)cg * 128) * LN;
        for (int c = 0; c < 128; c++){
            #pragma unroll
            for (int j = 0; j < 4; j++) acc[j] += xb[(size_t)c * LN + u + 256*j];
        }
        #pragma unroll
        for (int j = 0; j < 4; j++) atomicAdd(&d_s[b * LN + u + 256*j], acc[j]);
    } else {
        int b = blockIdx.x - 64;
        float2 a[4];
        #pragma unroll
        for (int j = 0; j < 4; j++) a[j] = make_float2(q[b * LN + u + 256*j], 0.f);
        fft1024<false>(a, S0, S1, u);
        #pragma unroll
        for (int j = 0; j < 4; j++) d_qf[b * LN + u + 256*j] = a[j];
    }
}

__global__ void k_stats(const float* __restrict__ q,
                        const float* __restrict__ sig,
                        const float* __restrict__ csh){
    __shared__ float2 S0[LN], S1[LN];
    __shared__ float gsh[16];
    __shared__ float ssb[LN];
    __shared__ float red[32];
    __shared__ float scal[4];
    int k = blockIdx.x, b = blockIdx.y, u = threadIdx.x;

    float sg = sig[k] + 0.001f;
    float cc = csh[k];
    if (u < 15){
        float t = (float)u - 7.0f - cc;
        gsh[u] = expf(-0.5f * (t / sg) * (t / sg));
    }
    #pragma unroll
    for (int j = 0; j < 4; j++) ssb[u + 256*j] = d_s[b * LN + u + 256*j];
    __syncthreads();

    float gs = 0.f;
    #pragma unroll
    for (int j = 0; j < 15; j++) gs += gsh[j];
    float g[15];
    float ginv = 1.0f / (gs + 0.01f);
    #pragma unroll
    for (int j = 0; j < 15; j++) g[j] = gsh[j] * ginv;

    float2 a[4];
    #pragma unroll
    for (int c = 0; c < 4; c++){
        int l = u + 256*c;
        float bl = 0.f;
        #pragma unroll
        for (int j = 0; j < 15; j++){
            int idx = l + j - 7;
            idx = idx < 0 ? 0 : (idx > LN-1 ? LN-1 : idx);
            bl += ssb[idx] * g[j];
        }
        a[c] = make_float2(bl, 0.f);
    }

    if (u == 0){
        float mxs = 0.f, mys = 0.f;
        for (int bb2 = 0; bb2 < NB; bb2++){
            float bl0 = 0.f;
            #pragma unroll
            for (int j = 0; j < 15; j++){
                int idx = j - 7; if (idx < 0) idx = 0;
                bl0 += d_s[bb2 * LN + idx] * g[j];
            }
            mxs += bl0;
            mys += q[bb2 * LN];
        }
        scal[0] = mxs * (1.0f/16.0f);
        scal[1] = mys * (1.0f/16.0f);
    }
    __syncthreads();

    fft1024<false>(a, S0, S1, u);

    float2 qf[4];
    #pragma unroll
    for (int c = 0; c < 4; c++) qf[c] = d_qf[b * LN + u + 256*c];

    float mx = scal[0], my = scal[1];

    float v0 = 0.f, v1 = 0.f, v2 = 0.f, v3 = 0.f;
    #pragma unroll
    for (int c = 0; c < 4; c++){
        float2 vm = a[c];  vm.x -= mx;
        float2 t  = cmul(vm, vm);
        v0 += t.x; v1 += t.y;
        float2 qm = qf[c]; qm.x -= mx;
        t = cmul(qm, qm);
        v2 += t.x; v3 += t.y;
    }
    #pragma unroll
    for (int o = 16; o > 0; o >>= 1){
        v0 += __shfl_down_sync(0xffffffffu, v0, o);
        v1 += __shfl_down_sync(0xffffffffu, v1, o);
        v2 += __shfl_down_sync(0xffffffffu, v2, o);
        v3 += __shfl_down_sync(0xffffffffu, v3, o);
    }
    if ((u & 31) == 0){
        int w = u >> 5;
        red[w*4+0] = v0; red[w*4+1] = v1; red[w*4+2] = v2; red[w*4+3] = v3;
    }
    __syncthreads();
    float2 AS = make_float2(0.f, 0.f), BS = make_float2(0.f, 0.f);
    #pragma unroll
    for (int w = 0; w < 8; w++){
        AS.x += red[w*4+0]; AS.y += red[w*4+1];
        BS.x += red[w*4+2]; BS.y += red[w*4+3];
    }
    float2 dd = cmul(AS, BS);
    dd.x += 0.001f;
    float dinv = rsqrtf(dd.x*dd.x + dd.y*dd.y);

    float2 pa[4];
    #pragma unroll
    for (int c = 0; c < 4; c++){
        float2 vm = a[c];  vm.x -= mx;
        float2 qm = qf[c]; qm.x -= my;
        float2 cov = cmul(vm, qm);
        float cm = sqrtf(cov.x*cov.x + cov.y*cov.y);
        float wv = 1.0f - expf(-0.1f * cm * dinv);
        // pre-scale by 1/1024 so k_main's ifft output needs no normalization
        d_w[(b * KN + k) * LN + u + 256*c] = wv * (1.0f/1024.0f);
        float om = 1.0f - wv;
        pa[c] = make_float2(om * qf[c].x, om * qf[c].y);
    }
    __syncthreads();
    fft1024<true>(pa, S0, S1, u);
    #pragma unroll
    for (int c = 0; c < 4; c++)
        d_p[(b * KN + k) * LN + u + 256*c] = pa[c].x * (1.0f/1024.0f);
}

// -------- main kernel: block per channel pair; two inverse FFTs packed per exchange --------
// (256,2): regs capped at 128 (R9's natural no-spill value).
__global__ void __launch_bounds__(256, 2) k_main(const float* __restrict__ x){
    __shared__ float4 S0[LN], S1[LN];   // 32 KB; also viewed as float2 for the forward FFT
    int cp = blockIdx.x;
    int b  = blockIdx.y;
    int u  = threadIdx.x;
    const float* x0 = x + ((size_t)b * NC + 2*cp    ) * LN;
    const float* x1 = x + ((size_t)b * NC + 2*cp + 1) * LN;

    float xa[4], xb[4];
    float2 z[4];
    #pragma unroll
    for (int j = 0; j < 4; j++){
        xa[j] = x0[u + 256*j];
        xb[j] = x1[u + 256*j];
        z[j] = make_float2(xa[j], xb[j]);
    }
    fft1024<false>(z, (float2*)S0, (float2*)S1, u);   // Z = X0 + i*X1

    float sm[4] = {0,0,0,0}, sq[4] = {0,0,0,0};
    __half2* ob = d_o + ((size_t)(b * NCP + cp)) * KN * LN;
    const float* wb = d_w + (size_t)b * KN * LN;
    const float* pb = d_p + (size_t)b * KN * LN;

    __syncthreads();   // forward FFT's last buffer reads before dual-stream overwrites

    for (int k = 0; k < KN; k += 2){
        float2 a[4], bb[4];
        #pragma unroll
        for (int j = 0; j < 4; j++){
            int l = u + 256*j;
            float wv0 = wb[ k      * LN + l];
            float wv1 = wb[(k + 1) * LN + l];
            a[j]  = make_float2(z[j].x * wv0, z[j].y * wv0);
            bb[j] = make_float2(z[j].x * wv1, z[j].y * wv1);
        }
        fft1024x2<true>(a, bb, S0, S1, u);
        #pragma unroll
        for (int j = 0; j < 4; j++){
            int l = u + 256*j;
            float pp0 = pb[ k      * LN + l];
            float pp1 = pb[(k + 1) * LN + l];
            float o0 = fabsf(a[j].x  + pp0) + xa[j];   // w pre-scaled by 1/1024
            float o1 = fabsf(a[j].y  + pp0) + xb[j];
            float o2 = fabsf(bb[j].x + pp1) + xa[j];
            float o3 = fabsf(bb[j].y + pp1) + xb[j];
            ob[ k      * LN + l] = __floats2half2_rn(o0, o1);
            ob[(k + 1) * LN + l] = __floats2half2_rn(o2, o3);
            sm[j] += (o0 + o1) + (o2 + o3);
            sq[j] += (o0*o0 + o1*o1) + (o2*o2 + o3*o3);
        }
        // no trailing barrier needed: stage-3 barrier inside fft1024x2 separates
        // the last S0 reads (stage-2) from the next call's stage-0 writes.
    }
    #pragma unroll
    for (int j = 0; j < 4; j++){
        atomicAdd(&d_sum[u + 256*j], sm[j]);
        atomicAdd(&d_sq[u + 256*j],  sq[j]);
    }
}

__global__ void k_bn(const float* __restrict__ gamma, const float* __restrict__ beta){
    int l = blockIdx.x * 256 + threadIdx.x;
    if (l < LN){
        float cnt  = (float)(NB * NC * KN);   // 65536
        float mean = d_sum[l] / cnt;
        float var  = d_sq[l] / cnt - mean * mean;
        float sc = gamma[l] * rsqrtf(var + 1e-5f);
        d_scale[l] = sc;
        d_shift[l] = beta[l] - mean * sc;
    }
}

__global__ void __launch_bounds__(256) k_attn(const float* __restrict__ q, float* __restrict__ out){
    __shared__ float red[8 * 16];
    int cp = blockIdx.x, b = blockIdx.y, u = threadIdx.x;
    const __half2* ob = d_o + ((size_t)(b * NCP + cp)) * KN * LN;

    float qa[4], sc[4], sh[4];
    #pragma unroll
    for (int j = 0; j < 4; j++){
        int l = u + 256*j;
        float sl = d_scale[l];
        qa[j] = q[b * LN + l] * sl;
        sc[j] = sl;
        sh[j] = d_shift[l];
    }
    __half2 ov[KN][4];
    float s0[KN], s1[KN];
    #pragma unroll
    for (int k = 0; k < KN; k++){ s0[k] = 0.f; s1[k] = 0.f; }
    #pragma unroll
    for (int k = 0; k < KN; k++){
        #pragma unroll
        for (int j = 0; j < 4; j++){
            __half2 h = ob[k * LN + u + 256*j];
            ov[k][j] = h;
            float2 f = __half22float2(h);
            s0[k] += qa[j] * f.x;
            s1[k] += qa[j] * f.y;
        }
    }
    #pragma unroll
    for (int k = 0; k < KN; k++){
        #pragma unroll
        for (int o = 16; o > 0; o >>= 1){
            s0[k] += __shfl_down_sync(0xffffffffu, s0[k], o);
            s1[k] += __shfl_down_sync(0xffffffffu, s1[k], o);
        }
    }
    if ((u & 31) == 0){
        int w = u >> 5;
        #pragma unroll
        for (int k = 0; k < KN; k++){
            red[w * 16 + k]     = s0[k];
            red[w * 16 + 8 + k] = s1[k];
        }
    }
    __syncthreads();
    float t0[KN], t1[KN];
    #pragma unroll
    for (int k = 0; k < KN; k++){
        float a0 = 0.f, a1 = 0.f;
        #pragma unroll
        for (int w = 0; w < 8; w++){
            a0 += red[w * 16 + k];
            a1 += red[w * 16 + 8 + k];
        }
        t0[k] = a0; t1[k] = a1;
    }
    float m0 = t0[0], m1 = t1[0];
    #pragma unroll
    for (int k = 1; k < KN; k++){ m0 = fmaxf(m0, t0[k]); m1 = fmaxf(m1, t1[k]); }
    float a0[KN], a1[KN], se0 = 0.f, se1 = 0.f;
    #pragma unroll
    for (int k = 0; k < KN; k++){
        a0[k] = expf(t0[k] - m0); se0 += a0[k];
        a1[k] = expf(t1[k] - m1); se1 += a1[k];
    }
    float i0 = 1.0f / se0, i1 = 1.0f / se1;
    float* o0p = out + ((size_t)b * NC + 2*cp    ) * LN;
    float* o1p = out + ((size_t)b * NC + 2*cp + 1) * LN;
    #pragma unroll
    for (int j = 0; j < 4; j++){
        float acc0 = 0.f, acc1 = 0.f;
        #pragma unroll
        for (int k = 0; k < KN; k++){
            float2 f = __half22float2(ov[k][j]);
            acc0 += a0[k] * f.x;
            acc1 += a1[k] * f.y;
        }
        int l = u + 256*j;
        o0p[l] = sc[j] * (acc0 * i0) + sh[j];
        o1p[l] = sc[j] * (acc1 * i1) + sh[j];
    }
}

extern "C" void kernel_launch(void* const* d_in, const int* in_sizes, int n_in,
                              void* d_out, int out_size){
    const float* x     = (const float*)d_in[0];
    const float* q     = (const float*)d_in[1];
    const float* sig   = (const float*)d_in[2];
    const float* csh   = (const float*)d_in[3];
    const float* gamma = (const float*)d_in[4];
    const float* beta  = (const float*)d_in[5];
    float* out = (float*)d_out;

    k_init <<<64, 256>>>();
    k_sumqf<<<80, 256>>>(x, q);
    k_stats<<<dim3(KN, NB), 256>>>(q, sig, csh);
    k_main <<<dim3(NCP, NB), 256>>>(x);
    k_bn   <<<4, 256>>>(gamma, beta);
    k_attn <<<dim3(NCP, NB), 256>>>(q, out);
}